// round 9
// baseline (speedup 1.0000x reference)
#include <cuda_runtime.h>
#include <cuda_fp16.h>
#include <math.h>
#include <stdint.h>

#define S0_    2048
#define BATCH_ 2
#define NHEAD_ 16
#define HDIM_  64
#define HID_   1024
#define FFN_   4096
#define NROWS_ (BATCH_ * S0_)          // 4096
#define QKVN_  3072
#define NEGF_  (-3.402823466e38f)
#define NEGI_  (-1.0e30f)

// Scratch (no cudaMalloc allowed) — device globals.
__device__ __half g_qkvh[(size_t)NROWS_ * QKVN_];   // fused q|k|v fp16, stride 3072
__device__ float  g_attn[(size_t)NROWS_ * HID_];
__device__ float  g_y[(size_t)NROWS_ * HID_];
__device__ __half g_yh[(size_t)NROWS_ * HID_];
__device__ __half g_xh[(size_t)NROWS_ * HID_];
__device__ __half g_hh[(size_t)NROWS_ * FFN_];
__device__ __half g_wqkv[(size_t)QKVN_ * HID_];     // [n][k], q-part pre-scaled by 1/8
__device__ __half g_w1t[(size_t)FFN_ * HID_];
__device__ __half g_w2t[(size_t)HID_ * FFN_];
__device__ float  g_bqkv[QKVN_];

// ---------------------------------------------------------------------------
__device__ __forceinline__ void mma_fp16(float* c, const uint32_t* a, const uint32_t* b) {
    asm volatile(
        "mma.sync.aligned.m16n8k16.row.col.f32.f16.f16.f32 "
        "{%0,%1,%2,%3}, {%4,%5,%6,%7}, {%8,%9}, {%0,%1,%2,%3};"
        : "+f"(c[0]), "+f"(c[1]), "+f"(c[2]), "+f"(c[3])
        : "r"(a[0]), "r"(a[1]), "r"(a[2]), "r"(a[3]), "r"(b[0]), "r"(b[1]));
}

__device__ __forceinline__ void ldsm4(uint32_t* r, uint32_t saddr) {
    asm volatile("ldmatrix.sync.aligned.m8n8.x4.shared.b16 {%0,%1,%2,%3}, [%4];"
                 : "=r"(r[0]), "=r"(r[1]), "=r"(r[2]), "=r"(r[3]) : "r"(saddr));
}

__device__ __forceinline__ uint32_t h2u(__half2 h) {
    union { __half2 h; uint32_t u; } cvt;
    cvt.h = h;
    return cvt.u;
}

__device__ __forceinline__ void cp16(void* smem, const void* gptr) {
    uint32_t s = (uint32_t)__cvta_generic_to_shared(smem);
    asm volatile("cp.async.cg.shared.global [%0], [%1], 16;" :: "r"(s), "l"(gptr));
}

// ---------------------------------------------------------------------------
// fp16 tensor-core GEMM: C[M,N] = epi(A[M,K] @ BT[N,K]^T + bias)
// 128x128 tile, BK=32, 3-stage cp.async pipeline, 8 warps (2x4), 64x32/warp.
// Fragment loads via ldmatrix.x4 (12 LDSM per warp-stage instead of 48 LDS).
// EPI 0: fp16 out.  EPI 1: exact gelu, fp16 out.  EPI 2: +res, fp32 out.
// ---------------------------------------------------------------------------
#define HG_SMEM (3 * 20480)

template <int EPI>
__global__ void __launch_bounds__(256, 2)
hgemm(const __half* __restrict__ A, const __half* __restrict__ BT,
      const float* __restrict__ bias, const float* __restrict__ res,
      void* __restrict__ Cout, int M, int N, int K)
{
    constexpr int RSTR = 80;                 // smem row stride bytes (40 halves)
    extern __shared__ __align__(16) uint8_t smg[];

    const int tid   = threadIdx.x;
    const int lane  = tid & 31;
    const int warp  = tid >> 5;
    const int warpM = warp & 1;
    const int warpN = warp >> 1;
    const int g     = lane >> 2;
    const int tg    = lane & 3;

    const int lrow = tid >> 1;
    const int lcp  = (tid & 1) * 2;
    const __half* Ag = A  + (size_t)(blockIdx.y * 128 + lrow) * K + lcp * 8;
    const __half* Bg = BT + (size_t)(blockIdx.x * 128 + lrow) * K + lcp * 8;
    const uint32_t sOff = lrow * RSTR + lcp * 16;

    // ldmatrix per-lane address offsets (within a stage buffer)
    const uint32_t aBase = (uint32_t)((warpM * 64 + (lane & 15)) * RSTR + (lane >> 4) * 16);
    const uint32_t bBase = (uint32_t)((warpN * 32 + (lane >> 4) * 8 + (lane & 7)) * RSTR
                                      + ((lane >> 3) & 1) * 16);

    float acc[4][4][4];
#pragma unroll
    for (int i = 0; i < 4; i++)
#pragma unroll
        for (int j = 0; j < 4; j++)
#pragma unroll
            for (int r = 0; r < 4; r++) acc[i][j][r] = 0.0f;

    const int nst = K >> 5;
    const uint32_t smgS = (uint32_t)__cvta_generic_to_shared(smg);

    // prologue: stages 0 and 1
#pragma unroll
    for (int p = 0; p < 2; p++) {
        uint8_t* sA = smg + p * 20480;
        uint8_t* sB = sA + 10240;
#pragma unroll
        for (int i = 0; i < 2; i++) {
            cp16(sA + sOff + i * 16, Ag + p * 32 + i * 8);
            cp16(sB + sOff + i * 16, Bg + p * 32 + i * 8);
        }
        asm volatile("cp.async.commit_group;");
    }

    for (int s = 0; s < nst; ++s) {
        asm volatile("cp.async.wait_group 1;" ::: "memory");
        __syncthreads();

        if (s + 2 < nst) {
            uint8_t* sA = smg + ((s + 2) % 3) * 20480;
            uint8_t* sB = sA + 10240;
            const int ko = (s + 2) * 32;
#pragma unroll
            for (int i = 0; i < 2; i++) {
                cp16(sA + sOff + i * 16, Ag + ko + i * 8);
                cp16(sB + sOff + i * 16, Bg + ko + i * 8);
            }
        }
        asm volatile("cp.async.commit_group;");

        const uint32_t cA = smgS + (s % 3) * 20480;
        const uint32_t cB = cA + 10240;
#pragma unroll
        for (int ks = 0; ks < 2; ks++) {
            const int kb = ks * 32;
            uint32_t af[4][4], bf[4][2];
#pragma unroll
            for (int mt = 0; mt < 4; mt++)
                ldsm4(af[mt], cA + aBase + mt * (16 * RSTR) + kb);
#pragma unroll
            for (int np = 0; np < 2; np++) {
                uint32_t r[4];
                ldsm4(r, cB + bBase + np * (16 * RSTR) + kb);
                bf[2 * np][0]     = r[0];
                bf[2 * np][1]     = r[1];
                bf[2 * np + 1][0] = r[2];
                bf[2 * np + 1][1] = r[3];
            }
#pragma unroll
            for (int mt = 0; mt < 4; mt++)
#pragma unroll
                for (int nt = 0; nt < 4; nt++)
                    mma_fp16(acc[mt][nt], af[mt], bf[nt]);
        }
    }

    const int rowBase = blockIdx.y * 128 + warpM * 64;
    const int colBase = blockIdx.x * 128 + warpN * 32;
#pragma unroll
    for (int mt = 0; mt < 4; mt++) {
#pragma unroll
        for (int nt = 0; nt < 4; nt++) {
            const int col = colBase + nt * 8 + 2 * tg;
            const float b0 = bias[col], b1 = bias[col + 1];
#pragma unroll
            for (int hf = 0; hf < 2; hf++) {
                const int row = rowBase + mt * 16 + g + 8 * hf;
                float v0 = acc[mt][nt][2 * hf + 0] + b0;
                float v1 = acc[mt][nt][2 * hf + 1] + b1;
                const size_t ro = (size_t)row * N + col;
                if (EPI == 0) {
                    *(__half2*)((__half*)Cout + ro) = __floats2half2_rn(v0, v1);
                } else if (EPI == 1) {
                    v0 = 0.5f * v0 * (1.0f + erff(v0 * 0.70710678118654752f));
                    v1 = 0.5f * v1 * (1.0f + erff(v1 * 0.70710678118654752f));
                    *(__half2*)((__half*)Cout + ro) = __floats2half2_rn(v0, v1);
                } else {
                    v0 += res[ro]; v1 += res[ro + 1];
                    float2 o; o.x = v0; o.y = v1;
                    *(float2*)((float*)Cout + ro) = o;
                }
            }
        }
    }
}

// ---------------------------------------------------------------------------
// Flash-style banded attention on tensor cores (unchanged from R8).
// ---------------------------------------------------------------------------
#define FA_SMEM 55296

__global__ void __launch_bounds__(256)
fattn_kernel(const __half* __restrict__ QKV, const float* __restrict__ bk,
             const float* __restrict__ bv, const int* __restrict__ mask,
             float* __restrict__ attn)
{
    extern __shared__ __align__(16) uint8_t sm[];
    __half* Qs  = (__half*)(sm);             // stride 72 halves
    __half* Ks  = (__half*)(sm + 18432);     // stride 72
    __half* Vt  = (__half*)(sm + 36864);     // [64][136]
    float*  mNEG = (float*)(sm + 54272);
    float*  sgs  = (float*)(sm + 54784);

    const int b  = blockIdx.x >> 4;
    const int h  = blockIdx.x & 15;
    const int q0 = blockIdx.y * 128;
    const int tid = threadIdx.x, lane = tid & 31, warp = tid >> 5;
    const int g = lane >> 2, tg = lane & 3;
    const int rw = warp * 16;

    const size_t qkvbase = (size_t)b * S0_ * QKVN_ + (size_t)h * HDIM_;

    // ---- load Q tile + compute global-key scores sgs[r] = q_r . bk_h
    {
        const int r  = tid >> 1;
        const int d0 = (tid & 1) * 32;
        const __half* src = QKV + qkvbase + (size_t)(q0 + r) * QKVN_ + d0;
        uint4 u[4];
#pragma unroll
        for (int i = 0; i < 4; i++) u[i] = *(const uint4*)(src + i * 8);
#pragma unroll
        for (int i = 0; i < 4; i++)
            *(uint4*)(Qs + r * 72 + d0 + i * 8) = u[i];

        const __half* hv = (const __half*)u;
        float a = 0.0f;
#pragma unroll
        for (int i = 0; i < 32; i++)
            a += __half2float(hv[i]) * bk[h * HDIM_ + d0 + i];
        a += __shfl_xor_sync(0xffffffffu, a, 1);
        if ((tid & 1) == 0) sgs[r] = a;
    }
    __syncthreads();

    // ---- Q fragments (A operand), loaded once
    uint32_t af[4][4];
#pragma unroll
    for (int kc = 0; kc < 4; kc++) {
        const __half* ap = Qs + (rw + g) * 72 + kc * 16 + 2 * tg;
        af[kc][0] = *(const uint32_t*)(ap);
        af[kc][1] = *(const uint32_t*)(ap + 8 * 72);
        af[kc][2] = *(const uint32_t*)(ap + 8);
        af[kc][3] = *(const uint32_t*)(ap + 8 * 72 + 8);
    }

    float m0 = NEGI_, m1 = NEGI_, l0 = 0.0f, l1 = 0.0f;
    float O[8][4];
#pragma unroll
    for (int i = 0; i < 8; i++)
#pragma unroll
        for (int j = 0; j < 4; j++) O[i][j] = 0.0f;

    for (int c = 0; c < 3; c++) {
        const int j0c = q0 - 128 + c * 128;
        if (j0c > S0_ - 1 || j0c + 127 < 0) continue;

        __syncthreads();
        {
            const int kk = tid >> 1;
            const int d0 = (tid & 1) * 32;
            int j  = j0c + kk;
            int jc = j < 0 ? 0 : (j > S0_ - 1 ? S0_ - 1 : j);
            const __half* ksrc = QKV + qkvbase + (size_t)jc * QKVN_ + HID_ + d0;
#pragma unroll
            for (int i = 0; i < 4; i++)
                *(uint4*)(Ks + kk * 72 + d0 + i * 8) = *(const uint4*)(ksrc + i * 8);

            const __half* vsrc = QKV + qkvbase + (size_t)jc * QKVN_ + 2 * HID_ + d0;
            uint4 u[4];
#pragma unroll
            for (int i = 0; i < 4; i++) u[i] = *(const uint4*)(vsrc + i * 8);
            const __half* hv = (const __half*)u;
#pragma unroll
            for (int i = 0; i < 32; i++)
                Vt[(d0 + i) * 136 + kk] = hv[i];

            if (tid < 128) {
                int jj = j0c + tid;
                mNEG[tid] = (jj < 0 || jj > S0_ - 1 || mask[b * S0_ + jj] != 0)
                              ? NEGF_ : 0.0f;
            }
        }
        __syncthreads();

        // ---- scores S[16 x 128]
        float s[16][4];
#pragma unroll
        for (int nt = 0; nt < 16; nt++) {
            s[nt][0] = s[nt][1] = s[nt][2] = s[nt][3] = 0.0f;
#pragma unroll
            for (int kc = 0; kc < 4; kc++) {
                uint32_t bf[2];
                const __half* bp = Ks + (nt * 8 + g) * 72 + kc * 16 + 2 * tg;
                bf[0] = *(const uint32_t*)(bp);
                bf[1] = *(const uint32_t*)(bp + 8);
                mma_fp16(s[nt], af[kc], bf);
            }
        }

        // ---- mask + row max
        const int base = 128 * c - rw - g;
        float mx0 = NEGI_, mx1 = NEGI_;
#pragma unroll
        for (int nt = 0; nt < 16; nt++) {
            const int col0 = nt * 8 + 2 * tg;
            const float mn0 = mNEG[col0], mn1 = mNEG[col0 + 1];
            const int d = base + col0;
            s[nt][0] = ((unsigned)d       <= 256u) ? s[nt][0] + mn0 : NEGF_;
            s[nt][1] = ((unsigned)(d + 1) <= 256u) ? s[nt][1] + mn1 : NEGF_;
            s[nt][2] = ((unsigned)(d - 8) <= 256u) ? s[nt][2] + mn0 : NEGF_;
            s[nt][3] = ((unsigned)(d - 7) <= 256u) ? s[nt][3] + mn1 : NEGF_;
            mx0 = fmaxf(mx0, fmaxf(s[nt][0], s[nt][1]));
            mx1 = fmaxf(mx1, fmaxf(s[nt][2], s[nt][3]));
        }
#pragma unroll
        for (int o = 1; o <= 2; o <<= 1) {
            mx0 = fmaxf(mx0, __shfl_xor_sync(0xffffffffu, mx0, o));
            mx1 = fmaxf(mx1, __shfl_xor_sync(0xffffffffu, mx1, o));
        }

        const float mn0 = fmaxf(fmaxf(m0, mx0), NEGI_);
        const float mn1 = fmaxf(fmaxf(m1, mx1), NEGI_);
        const float sc0 = __expf(m0 - mn0);
        const float sc1 = __expf(m1 - mn1);
        m0 = mn0; m1 = mn1;

        float rs0 = 0.0f, rs1 = 0.0f;
#pragma unroll
        for (int nt = 0; nt < 16; nt++) {
            s[nt][0] = __expf(s[nt][0] - mn0);
            s[nt][1] = __expf(s[nt][1] - mn0);
            s[nt][2] = __expf(s[nt][2] - mn1);
            s[nt][3] = __expf(s[nt][3] - mn1);
            rs0 += s[nt][0] + s[nt][1];
            rs1 += s[nt][2] + s[nt][3];
        }
#pragma unroll
        for (int o = 1; o <= 2; o <<= 1) {
            rs0 += __shfl_xor_sync(0xffffffffu, rs0, o);
            rs1 += __shfl_xor_sync(0xffffffffu, rs1, o);
        }
        l0 = l0 * sc0 + rs0;
        l1 = l1 * sc1 + rs1;
#pragma unroll
        for (int on = 0; on < 8; on++) {
            O[on][0] *= sc0; O[on][1] *= sc0;
            O[on][2] *= sc1; O[on][3] *= sc1;
        }

        // ---- P V  (P from C-frags as A-frags)
#pragma unroll
        for (int kc2 = 0; kc2 < 8; kc2++) {
            uint32_t pa[4];
            pa[0] = h2u(__floats2half2_rn(s[2 * kc2][0],     s[2 * kc2][1]));
            pa[1] = h2u(__floats2half2_rn(s[2 * kc2][2],     s[2 * kc2][3]));
            pa[2] = h2u(__floats2half2_rn(s[2 * kc2 + 1][0], s[2 * kc2 + 1][1]));
            pa[3] = h2u(__floats2half2_rn(s[2 * kc2 + 1][2], s[2 * kc2 + 1][3]));
#pragma unroll
            for (int on = 0; on < 8; on++) {
                uint32_t bf[2];
                const __half* bp = Vt + (on * 8 + g) * 136 + kc2 * 16 + 2 * tg;
                bf[0] = *(const uint32_t*)(bp);
                bf[1] = *(const uint32_t*)(bp + 8);
                mma_fp16(O[on], pa, bf);
            }
        }
    }

    // ---- fold in global key + normalize + write
    const float sg0 = sgs[rw + g];
    const float sg1 = sgs[rw + g + 8];
    const float mf0 = fmaxf(m0, sg0), mf1 = fmaxf(m1, sg1);
    const float sc0 = __expf(m0 - mf0), sc1 = __expf(m1 - mf1);
    const float pg0 = __expf(sg0 - mf0), pg1 = __expf(sg1 - mf1);
    l0 = l0 * sc0 + pg0;
    l1 = l1 * sc1 + pg1;

    const int r0 = q0 + rw + g;
    const int r1 = r0 + 8;
    const float inv0 = (mask[b * S0_ + r0] != 0) ? 0.0f : 1.0f / l0;
    const float inv1 = (mask[b * S0_ + r1] != 0) ? 0.0f : 1.0f / l1;

#pragma unroll
    for (int on = 0; on < 8; on++) {
        const int dcol = on * 8 + 2 * tg;
        const float bv0 = bv[h * HDIM_ + dcol];
        const float bv1 = bv[h * HDIM_ + dcol + 1];
        float2 o0, o1;
        o0.x = (O[on][0] * sc0 + pg0 * bv0) * inv0;
        o0.y = (O[on][1] * sc0 + pg0 * bv1) * inv0;
        o1.x = (O[on][2] * sc1 + pg1 * bv0) * inv1;
        o1.y = (O[on][3] * sc1 + pg1 * bv1) * inv1;
        *(float2*)(attn + (size_t)(b * S0_ + r0) * HID_ + h * HDIM_ + dcol) = o0;
        *(float2*)(attn + (size_t)(b * S0_ + r1) * HID_ + h * HDIM_ + dcol) = o1;
    }
}

// ---------------------------------------------------------------------------
// Weight transpose + fp32->fp16 (+scale):  WT[n*K+k] = half(W[k*N+n]*scale)
// ---------------------------------------------------------------------------
__global__ void transcvt_kernel(const float* __restrict__ W, __half* __restrict__ WT,
                                int K, int N, float scale)
{
    __shared__ float t[32][33];
    const int n0 = blockIdx.x * 32, k0 = blockIdx.y * 32;
    const int x = threadIdx.x, y = threadIdx.y;
#pragma unroll
    for (int i = 0; i < 32; i += 8)
        t[y + i][x] = W[(size_t)(k0 + y + i) * N + n0 + x] * scale;
    __syncthreads();
#pragma unroll
    for (int i = 0; i < 32; i += 8)
        WT[(size_t)(n0 + y + i) * K + k0 + x] = __float2half(t[x][y + i]);
}

__global__ void cvtx_kernel(const float* __restrict__ x, __half* __restrict__ xh, int n4)
{
    const int i = blockIdx.x * blockDim.x + threadIdx.x;
    if (i >= n4) return;
    const float4 v = ((const float4*)x)[i];
    __half2* o = (__half2*)xh + i * 2;
    o[0] = __floats2half2_rn(v.x, v.y);
    o[1] = __floats2half2_rn(v.z, v.w);
}

__global__ void bias_kernel(const float* __restrict__ bq, const float* __restrict__ bk,
                            const float* __restrict__ bv, float* __restrict__ bqkv)
{
    const int i = blockIdx.x * blockDim.x + threadIdx.x;
    if (i < HID_)            bqkv[i] = bq[i] * 0.125f;
    else if (i < 2 * HID_)   bqkv[i] = bk[i - HID_];
    else if (i < 3 * HID_)   bqkv[i] = bv[i - 2 * HID_];
}

// ---------------------------------------------------------------------------
// y = LayerNorm(x + attn) * g + b   (fp32 out + fp16 copy)
// ---------------------------------------------------------------------------
__global__ void ln_kernel(const float* __restrict__ x, const float* __restrict__ attn,
                          const float* __restrict__ gg, const float* __restrict__ bb,
                          float* __restrict__ y, __half* __restrict__ yh)
{
    const int row = blockIdx.x;
    const int t   = threadIdx.x;

    const float4 xv = ((const float4*)(x + (size_t)row * HID_))[t];
    const float4 av = ((const float4*)(attn + (size_t)row * HID_))[t];
    const float v0 = xv.x + av.x, v1 = xv.y + av.y, v2 = xv.z + av.z, v3 = xv.w + av.w;

    float s  = v0 + v1 + v2 + v3;
    float ss = v0 * v0 + v1 * v1 + v2 * v2 + v3 * v3;

    __shared__ float shs[8], shss[8], stats[2];
#pragma unroll
    for (int o = 16; o; o >>= 1) {
        s  += __shfl_xor_sync(0xffffffffu, s, o);
        ss += __shfl_xor_sync(0xffffffffu, ss, o);
    }
    if ((t & 31) == 0) { shs[t >> 5] = s; shss[t >> 5] = ss; }
    __syncthreads();
    if (t == 0) {
        float S = 0.0f, SS = 0.0f;
#pragma unroll
        for (int i = 0; i < 8; i++) { S += shs[i]; SS += shss[i]; }
        const float mu  = S * (1.0f / HID_);
        const float var = SS * (1.0f / HID_) - mu * mu;
        stats[0] = mu;
        stats[1] = rsqrtf(var + 1e-5f);
    }
    __syncthreads();
    const float mu = stats[0], rs = stats[1];

    const float4 g4 = ((const float4*)gg)[t];
    const float4 b4 = ((const float4*)bb)[t];
    float4 o;
    o.x = (v0 - mu) * rs * g4.x + b4.x;
    o.y = (v1 - mu) * rs * g4.y + b4.y;
    o.z = (v2 - mu) * rs * g4.z + b4.z;
    o.w = (v3 - mu) * rs * g4.w + b4.w;
    ((float4*)(y + (size_t)row * HID_))[t] = o;

    __half2* oh = (__half2*)(yh + (size_t)row * HID_) + t * 2;
    oh[0] = __floats2half2_rn(o.x, o.y);
    oh[1] = __floats2half2_rn(o.z, o.w);
}

// ---------------------------------------------------------------------------
extern "C" void kernel_launch(void* const* d_in, const int* in_sizes, int n_in,
                              void* d_out, int out_size)
{
    const float* x    = (const float*)d_in[0];
    const int*   mask = (const int*)  d_in[1];
    const float* wq = (const float*)d_in[2];
    const float* bq = (const float*)d_in[3];
    const float* wk = (const float*)d_in[4];
    const float* bk = (const float*)d_in[5];
    const float* wv = (const float*)d_in[6];
    const float* bv = (const float*)d_in[7];
    // d_in[8..13] dead (global-attention branch is sliced away by [:, :s0]).
    const float* ln_g = (const float*)d_in[14];
    const float* ln_b = (const float*)d_in[15];
    const float* w1 = (const float*)d_in[16];
    const float* b1 = (const float*)d_in[17];
    const float* w2 = (const float*)d_in[18];
    const float* b2 = (const float*)d_in[19];
    float* out = (float*)d_out;

    float *attn, *y, *bqkv;
    __half *qkvh, *yh, *xh, *hh, *wqkv, *w1t, *w2t;
    cudaGetSymbolAddress((void**)&qkvh, g_qkvh);
    cudaGetSymbolAddress((void**)&attn, g_attn);
    cudaGetSymbolAddress((void**)&y,    g_y);
    cudaGetSymbolAddress((void**)&yh,   g_yh);
    cudaGetSymbolAddress((void**)&xh,   g_xh);
    cudaGetSymbolAddress((void**)&hh,   g_hh);
    cudaGetSymbolAddress((void**)&wqkv, g_wqkv);
    cudaGetSymbolAddress((void**)&w1t,  g_w1t);
    cudaGetSymbolAddress((void**)&w2t,  g_w2t);
    cudaGetSymbolAddress((void**)&bqkv, g_bqkv);

    cudaFuncSetAttribute(hgemm<0>, cudaFuncAttributeMaxDynamicSharedMemorySize, HG_SMEM);
    cudaFuncSetAttribute(hgemm<1>, cudaFuncAttributeMaxDynamicSharedMemorySize, HG_SMEM);
    cudaFuncSetAttribute(hgemm<2>, cudaFuncAttributeMaxDynamicSharedMemorySize, HG_SMEM);
    cudaFuncSetAttribute(fattn_kernel, cudaFuncAttributeMaxDynamicSharedMemorySize, FA_SMEM);

    const dim3 tb(32, 8);
    transcvt_kernel<<<dim3(32, 32), tb>>>(wq, wqkv,               HID_, HID_, 0.125f);
    transcvt_kernel<<<dim3(32, 32), tb>>>(wk, wqkv + 1024 * HID_, HID_, HID_, 1.0f);
    transcvt_kernel<<<dim3(32, 32), tb>>>(wv, wqkv + 2048 * HID_, HID_, HID_, 1.0f);
    transcvt_kernel<<<dim3(FFN_ / 32, HID_ / 32), tb>>>(w1, w1t, HID_, FFN_, 1.0f);
    transcvt_kernel<<<dim3(HID_ / 32, FFN_ / 32), tb>>>(w2, w2t, FFN_, HID_, 1.0f);
    bias_kernel<<<QKVN_ / 256, 256>>>(bq, bk, bv, bqkv);
    cvtx_kernel<<<(NROWS_ * HID_ / 4 + 255) / 256, 256>>>(x, xh, NROWS_ * HID_ / 4);

    // fused QKV projection -> fp16
    hgemm<0><<<dim3(QKVN_ / 128, NROWS_ / 128), 256, HG_SMEM>>>(
        xh, wqkv, bqkv, nullptr, qkvh, NROWS_, QKVN_, HID_);

    fattn_kernel<<<dim3(BATCH_ * NHEAD_, S0_ / 128), 256, FA_SMEM>>>(
        qkvh, bk, bv, mask, attn);

    ln_kernel<<<NROWS_, 256>>>(x, attn, ln_g, ln_b, y, yh);

    hgemm<1><<<dim3(FFN_ / 128, NROWS_ / 128), 256, HG_SMEM>>>(
        yh, w1t, b1, nullptr, hh, NROWS_, FFN_, HID_);
    hgemm<2><<<dim3(HID_ / 128, NROWS_ / 128), 256, HG_SMEM>>>(
        hh, w2t, b2, y, out, NROWS_, HID_, FFN_);
}

// round 12
// speedup vs baseline: 1.3310x; 1.3310x over previous
#include <cuda_runtime.h>
#include <cuda_fp16.h>
#include <math.h>
#include <stdint.h>

#define S0_    2048
#define BATCH_ 2
#define NHEAD_ 16
#define HDIM_  64
#define HID_   1024
#define FFN_   4096
#define NROWS_ (BATCH_ * S0_)          // 4096
#define QKVN_  3072
#define NEGF_  (-3.402823466e38f)
#define NEGI_  (-1.0e30f)

// Scratch (no cudaMalloc allowed) — device globals.
__device__ __half g_qkvh[(size_t)NROWS_ * QKVN_];   // fused q|k|v fp16, stride 3072
__device__ float  g_attn[(size_t)NROWS_ * HID_];
__device__ float  g_y[(size_t)NROWS_ * HID_];
__device__ __half g_yh[(size_t)NROWS_ * HID_];
__device__ __half g_xh[(size_t)NROWS_ * HID_];
__device__ __half g_hh[(size_t)NROWS_ * FFN_];
__device__ __half g_wqkv[(size_t)QKVN_ * HID_];     // [n][k], q-part pre-scaled by 1/8
__device__ __half g_w1t[(size_t)FFN_ * HID_];
__device__ __half g_w2t[(size_t)HID_ * FFN_];
__device__ float  g_bqkv[QKVN_];

// ---------------------------------------------------------------------------
__device__ __forceinline__ void mma_fp16(float* c, const uint32_t* a, const uint32_t* b) {
    asm volatile(
        "mma.sync.aligned.m16n8k16.row.col.f32.f16.f16.f32 "
        "{%0,%1,%2,%3}, {%4,%5,%6,%7}, {%8,%9}, {%0,%1,%2,%3};"
        : "+f"(c[0]), "+f"(c[1]), "+f"(c[2]), "+f"(c[3])
        : "r"(a[0]), "r"(a[1]), "r"(a[2]), "r"(a[3]), "r"(b[0]), "r"(b[1]));
}

__device__ __forceinline__ uint32_t h2u(__half2 h) {
    union { __half2 h; uint32_t u; } cvt;
    cvt.h = h;
    return cvt.u;
}

__device__ __forceinline__ void cp16(void* smem, const void* gptr) {
    uint32_t s = (uint32_t)__cvta_generic_to_shared(smem);
    asm volatile("cp.async.cg.shared.global [%0], [%1], 16;" :: "r"(s), "l"(gptr));
}

// ---------------------------------------------------------------------------
// fp16 tensor-core GEMM: C[M,N] = epi(A[M,K] @ BT[N,K]^T + bias)
// 128x128 tile, BK=32, 4-stage cp.async pipeline (wait_group 2),
// 8 warps (2x4), 64x32/warp, direct LDS.32 fragment loads (R8-proven).
// EPI 0: fp16 out.  EPI 1: exact gelu, fp16 out.  EPI 2: +res, fp32 out.
// ---------------------------------------------------------------------------
#define HG_SMEM (4 * 20480)

template <int EPI>
__global__ void __launch_bounds__(256, 2)
hgemm(const __half* __restrict__ A, const __half* __restrict__ BT,
      const float* __restrict__ bias, const float* __restrict__ res,
      void* __restrict__ Cout, int M, int N, int K)
{
    constexpr int RSTR = 80;                 // smem row stride bytes (40 halves)
    extern __shared__ __align__(16) uint8_t smg[];

    const int tid   = threadIdx.x;
    const int lane  = tid & 31;
    const int warp  = tid >> 5;
    const int warpM = warp & 1;
    const int warpN = warp >> 1;
    const int g     = lane >> 2;
    const int tg    = lane & 3;

    const int lrow = tid >> 1;
    const int lcp  = (tid & 1) * 2;
    const __half* Ag = A  + (size_t)(blockIdx.y * 128 + lrow) * K + lcp * 8;
    const __half* Bg = BT + (size_t)(blockIdx.x * 128 + lrow) * K + lcp * 8;
    const uint32_t sOff = lrow * RSTR + lcp * 16;

    float acc[4][4][4];
#pragma unroll
    for (int i = 0; i < 4; i++)
#pragma unroll
        for (int j = 0; j < 4; j++)
#pragma unroll
            for (int r = 0; r < 4; r++) acc[i][j][r] = 0.0f;

    const int nst = K >> 5;

    // prologue: stages 0..2
#pragma unroll
    for (int p = 0; p < 3; p++) {
        uint8_t* sA = smg + p * 20480;
        uint8_t* sB = sA + 10240;
#pragma unroll
        for (int i = 0; i < 2; i++) {
            cp16(sA + sOff + i * 16, Ag + p * 32 + i * 8);
            cp16(sB + sOff + i * 16, Bg + p * 32 + i * 8);
        }
        asm volatile("cp.async.commit_group;");
    }

    for (int s = 0; s < nst; ++s) {
        asm volatile("cp.async.wait_group 2;" ::: "memory");
        __syncthreads();

        if (s + 3 < nst) {
            uint8_t* sA = smg + ((s + 3) & 3) * 20480;
            uint8_t* sB = sA + 10240;
            const int ko = (s + 3) * 32;
#pragma unroll
            for (int i = 0; i < 2; i++) {
                cp16(sA + sOff + i * 16, Ag + ko + i * 8);
                cp16(sB + sOff + i * 16, Bg + ko + i * 8);
            }
        }
        asm volatile("cp.async.commit_group;");

        const uint8_t* cA = smg + (s & 3) * 20480;
        const uint8_t* cB = cA + 10240;
#pragma unroll
        for (int ks = 0; ks < 2; ks++) {
            const int kb = ks * 32;
            uint32_t af[4][4], bf[4][2];
#pragma unroll
            for (int mt = 0; mt < 4; mt++) {
                const uint8_t* ap = cA + (warpM * 64 + mt * 16 + g) * RSTR + kb + tg * 4;
                af[mt][0] = *(const uint32_t*)(ap);
                af[mt][1] = *(const uint32_t*)(ap + 8 * RSTR);
                af[mt][2] = *(const uint32_t*)(ap + 16);
                af[mt][3] = *(const uint32_t*)(ap + 8 * RSTR + 16);
            }
#pragma unroll
            for (int nt = 0; nt < 4; nt++) {
                const uint8_t* bp = cB + (warpN * 32 + nt * 8 + g) * RSTR + kb + tg * 4;
                bf[nt][0] = *(const uint32_t*)(bp);
                bf[nt][1] = *(const uint32_t*)(bp + 16);
            }
#pragma unroll
            for (int mt = 0; mt < 4; mt++)
#pragma unroll
                for (int nt = 0; nt < 4; nt++)
                    mma_fp16(acc[mt][nt], af[mt], bf[nt]);
        }
    }

    const int rowBase = blockIdx.y * 128 + warpM * 64;
    const int colBase = blockIdx.x * 128 + warpN * 32;
#pragma unroll
    for (int mt = 0; mt < 4; mt++) {
#pragma unroll
        for (int nt = 0; nt < 4; nt++) {
            const int col = colBase + nt * 8 + 2 * tg;
            const float b0 = bias[col], b1 = bias[col + 1];
#pragma unroll
            for (int hf = 0; hf < 2; hf++) {
                const int row = rowBase + mt * 16 + g + 8 * hf;
                float v0 = acc[mt][nt][2 * hf + 0] + b0;
                float v1 = acc[mt][nt][2 * hf + 1] + b1;
                const size_t ro = (size_t)row * N + col;
                if (EPI == 0) {
                    *(__half2*)((__half*)Cout + ro) = __floats2half2_rn(v0, v1);
                } else if (EPI == 1) {
                    v0 = 0.5f * v0 * (1.0f + erff(v0 * 0.70710678118654752f));
                    v1 = 0.5f * v1 * (1.0f + erff(v1 * 0.70710678118654752f));
                    *(__half2*)((__half*)Cout + ro) = __floats2half2_rn(v0, v1);
                } else {
                    v0 += res[ro]; v1 += res[ro + 1];
                    float2 o; o.x = v0; o.y = v1;
                    *(float2*)((float*)Cout + ro) = o;
                }
            }
        }
    }
}

// ---------------------------------------------------------------------------
// Flash-style banded attention on tensor cores (unchanged from R8).
// ---------------------------------------------------------------------------
#define FA_SMEM 55296

__global__ void __launch_bounds__(256)
fattn_kernel(const __half* __restrict__ QKV, const float* __restrict__ bk,
             const float* __restrict__ bv, const int* __restrict__ mask,
             float* __restrict__ attn)
{
    extern __shared__ __align__(16) uint8_t sm[];
    __half* Qs  = (__half*)(sm);             // stride 72 halves
    __half* Ks  = (__half*)(sm + 18432);     // stride 72
    __half* Vt  = (__half*)(sm + 36864);     // [64][136]
    float*  mNEG = (float*)(sm + 54272);
    float*  sgs  = (float*)(sm + 54784);

    const int b  = blockIdx.x >> 4;
    const int h  = blockIdx.x & 15;
    const int q0 = blockIdx.y * 128;
    const int tid = threadIdx.x, lane = tid & 31, warp = tid >> 5;
    const int g = lane >> 2, tg = lane & 3;
    const int rw = warp * 16;

    const size_t qkvbase = (size_t)b * S0_ * QKVN_ + (size_t)h * HDIM_;

    // ---- load Q tile + compute global-key scores sgs[r] = q_r . bk_h
    {
        const int r  = tid >> 1;
        const int d0 = (tid & 1) * 32;
        const __half* src = QKV + qkvbase + (size_t)(q0 + r) * QKVN_ + d0;
        uint4 u[4];
#pragma unroll
        for (int i = 0; i < 4; i++) u[i] = *(const uint4*)(src + i * 8);
#pragma unroll
        for (int i = 0; i < 4; i++)
            *(uint4*)(Qs + r * 72 + d0 + i * 8) = u[i];

        const __half* hv = (const __half*)u;
        float a = 0.0f;
#pragma unroll
        for (int i = 0; i < 32; i++)
            a += __half2float(hv[i]) * bk[h * HDIM_ + d0 + i];
        a += __shfl_xor_sync(0xffffffffu, a, 1);
        if ((tid & 1) == 0) sgs[r] = a;
    }
    __syncthreads();

    // ---- Q fragments (A operand), loaded once
    uint32_t af[4][4];
#pragma unroll
    for (int kc = 0; kc < 4; kc++) {
        const __half* ap = Qs + (rw + g) * 72 + kc * 16 + 2 * tg;
        af[kc][0] = *(const uint32_t*)(ap);
        af[kc][1] = *(const uint32_t*)(ap + 8 * 72);
        af[kc][2] = *(const uint32_t*)(ap + 8);
        af[kc][3] = *(const uint32_t*)(ap + 8 * 72 + 8);
    }

    float m0 = NEGI_, m1 = NEGI_, l0 = 0.0f, l1 = 0.0f;
    float O[8][4];
#pragma unroll
    for (int i = 0; i < 8; i++)
#pragma unroll
        for (int j = 0; j < 4; j++) O[i][j] = 0.0f;

    for (int c = 0; c < 3; c++) {
        const int j0c = q0 - 128 + c * 128;
        if (j0c > S0_ - 1 || j0c + 127 < 0) continue;

        __syncthreads();
        {
            const int kk = tid >> 1;
            const int d0 = (tid & 1) * 32;
            int j  = j0c + kk;
            int jc = j < 0 ? 0 : (j > S0_ - 1 ? S0_ - 1 : j);
            const __half* ksrc = QKV + qkvbase + (size_t)jc * QKVN_ + HID_ + d0;
#pragma unroll
            for (int i = 0; i < 4; i++)
                *(uint4*)(Ks + kk * 72 + d0 + i * 8) = *(const uint4*)(ksrc + i * 8);

            const __half* vsrc = QKV + qkvbase + (size_t)jc * QKVN_ + 2 * HID_ + d0;
            uint4 u[4];
#pragma unroll
            for (int i = 0; i < 4; i++) u[i] = *(const uint4*)(vsrc + i * 8);
            const __half* hv = (const __half*)u;
#pragma unroll
            for (int i = 0; i < 32; i++)
                Vt[(d0 + i) * 136 + kk] = hv[i];

            if (tid < 128) {
                int jj = j0c + tid;
                mNEG[tid] = (jj < 0 || jj > S0_ - 1 || mask[b * S0_ + jj] != 0)
                              ? NEGF_ : 0.0f;
            }
        }
        __syncthreads();

        // ---- scores S[16 x 128]
        float s[16][4];
#pragma unroll
        for (int nt = 0; nt < 16; nt++) {
            s[nt][0] = s[nt][1] = s[nt][2] = s[nt][3] = 0.0f;
#pragma unroll
            for (int kc = 0; kc < 4; kc++) {
                uint32_t bf[2];
                const __half* bp = Ks + (nt * 8 + g) * 72 + kc * 16 + 2 * tg;
                bf[0] = *(const uint32_t*)(bp);
                bf[1] = *(const uint32_t*)(bp + 8);
                mma_fp16(s[nt], af[kc], bf);
            }
        }

        // ---- mask + row max
        const int base = 128 * c - rw - g;
        float mx0 = NEGI_, mx1 = NEGI_;
#pragma unroll
        for (int nt = 0; nt < 16; nt++) {
            const int col0 = nt * 8 + 2 * tg;
            const float mn0 = mNEG[col0], mn1 = mNEG[col0 + 1];
            const int d = base + col0;
            s[nt][0] = ((unsigned)d       <= 256u) ? s[nt][0] + mn0 : NEGF_;
            s[nt][1] = ((unsigned)(d + 1) <= 256u) ? s[nt][1] + mn1 : NEGF_;
            s[nt][2] = ((unsigned)(d - 8) <= 256u) ? s[nt][2] + mn0 : NEGF_;
            s[nt][3] = ((unsigned)(d - 7) <= 256u) ? s[nt][3] + mn1 : NEGF_;
            mx0 = fmaxf(mx0, fmaxf(s[nt][0], s[nt][1]));
            mx1 = fmaxf(mx1, fmaxf(s[nt][2], s[nt][3]));
        }
#pragma unroll
        for (int o = 1; o <= 2; o <<= 1) {
            mx0 = fmaxf(mx0, __shfl_xor_sync(0xffffffffu, mx0, o));
            mx1 = fmaxf(mx1, __shfl_xor_sync(0xffffffffu, mx1, o));
        }

        const float mn0 = fmaxf(fmaxf(m0, mx0), NEGI_);
        const float mn1 = fmaxf(fmaxf(m1, mx1), NEGI_);
        const float sc0 = __expf(m0 - mn0);
        const float sc1 = __expf(m1 - mn1);
        m0 = mn0; m1 = mn1;

        float rs0 = 0.0f, rs1 = 0.0f;
#pragma unroll
        for (int nt = 0; nt < 16; nt++) {
            s[nt][0] = __expf(s[nt][0] - mn0);
            s[nt][1] = __expf(s[nt][1] - mn0);
            s[nt][2] = __expf(s[nt][2] - mn1);
            s[nt][3] = __expf(s[nt][3] - mn1);
            rs0 += s[nt][0] + s[nt][1];
            rs1 += s[nt][2] + s[nt][3];
        }
#pragma unroll
        for (int o = 1; o <= 2; o <<= 1) {
            rs0 += __shfl_xor_sync(0xffffffffu, rs0, o);
            rs1 += __shfl_xor_sync(0xffffffffu, rs1, o);
        }
        l0 = l0 * sc0 + rs0;
        l1 = l1 * sc1 + rs1;
#pragma unroll
        for (int on = 0; on < 8; on++) {
            O[on][0] *= sc0; O[on][1] *= sc0;
            O[on][2] *= sc1; O[on][3] *= sc1;
        }

        // ---- P V  (P from C-frags as A-frags)
#pragma unroll
        for (int kc2 = 0; kc2 < 8; kc2++) {
            uint32_t pa[4];
            pa[0] = h2u(__floats2half2_rn(s[2 * kc2][0],     s[2 * kc2][1]));
            pa[1] = h2u(__floats2half2_rn(s[2 * kc2][2],     s[2 * kc2][3]));
            pa[2] = h2u(__floats2half2_rn(s[2 * kc2 + 1][0], s[2 * kc2 + 1][1]));
            pa[3] = h2u(__floats2half2_rn(s[2 * kc2 + 1][2], s[2 * kc2 + 1][3]));
#pragma unroll
            for (int on = 0; on < 8; on++) {
                uint32_t bf[2];
                const __half* bp = Vt + (on * 8 + g) * 136 + kc2 * 16 + 2 * tg;
                bf[0] = *(const uint32_t*)(bp);
                bf[1] = *(const uint32_t*)(bp + 8);
                mma_fp16(O[on], pa, bf);
            }
        }
    }

    // ---- fold in global key + normalize + write
    const float sg0 = sgs[rw + g];
    const float sg1 = sgs[rw + g + 8];
    const float mf0 = fmaxf(m0, sg0), mf1 = fmaxf(m1, sg1);
    const float sc0 = __expf(m0 - mf0), sc1 = __expf(m1 - mf1);
    const float pg0 = __expf(sg0 - mf0), pg1 = __expf(sg1 - mf1);
    l0 = l0 * sc0 + pg0;
    l1 = l1 * sc1 + pg1;

    const int r0 = q0 + rw + g;
    const int r1 = r0 + 8;
    const float inv0 = (mask[b * S0_ + r0] != 0) ? 0.0f : 1.0f / l0;
    const float inv1 = (mask[b * S0_ + r1] != 0) ? 0.0f : 1.0f / l1;

#pragma unroll
    for (int on = 0; on < 8; on++) {
        const int dcol = on * 8 + 2 * tg;
        const float bv0 = bv[h * HDIM_ + dcol];
        const float bv1 = bv[h * HDIM_ + dcol + 1];
        float2 o0, o1;
        o0.x = (O[on][0] * sc0 + pg0 * bv0) * inv0;
        o0.y = (O[on][1] * sc0 + pg0 * bv1) * inv0;
        o1.x = (O[on][2] * sc1 + pg1 * bv0) * inv1;
        o1.y = (O[on][3] * sc1 + pg1 * bv1) * inv1;
        *(float2*)(attn + (size_t)(b * S0_ + r0) * HID_ + h * HDIM_ + dcol) = o0;
        *(float2*)(attn + (size_t)(b * S0_ + r1) * HID_ + h * HDIM_ + dcol) = o1;
    }
}

// ---------------------------------------------------------------------------
// Fused prep: all weight transposes (+fp16, +scale), bias concat, x->fp16.
// Block budget (each partition re-derived from element counts):
//   [0, 4096)       : w1 tiles   (K=1024, N=4096 -> 32*128 = 4096 tiles)
//   [4096, 8192)    : w2 tiles   (K=4096, N=1024 -> 128*32 = 4096 tiles)
//   [8192, 11264)   : wq|wk|wv   (3 x 32*32 = 3072 tiles)
//   [11264, 11276)  : bias concat (3072 floats, 12 blocks x 256)
//   [11276, 15372)  : x -> fp16  (4096*1024/4 = 1,048,576 float4, 4096 blocks x 256)
// ---------------------------------------------------------------------------
#define PREP_BLOCKS 15372

__global__ void __launch_bounds__(256)
prep_kernel(const float* __restrict__ wq, const float* __restrict__ wk,
            const float* __restrict__ wv, const float* __restrict__ w1,
            const float* __restrict__ w2,
            const float* __restrict__ bq, const float* __restrict__ bk,
            const float* __restrict__ bv, const float* __restrict__ x,
            __half* __restrict__ wqkv, __half* __restrict__ w1t,
            __half* __restrict__ w2t, float* __restrict__ bqkv,
            __half* __restrict__ xh)
{
    const int bid = blockIdx.x;
    const int t   = threadIdx.x;
    const int tx  = t & 31, ty = t >> 5;

    if (bid < 11264) {
        // transpose one 32x32 tile: WT[n*K+k] = half(W[k*N+n]*scale)
        const float* W; __half* WT; int K, N, tile; float scale = 1.0f;
        if (bid < 4096)      { W = w1; WT = w1t; K = HID_; N = FFN_; tile = bid; }
        else if (bid < 8192) { W = w2; WT = w2t; K = FFN_; N = HID_; tile = bid - 4096; }
        else {
            const int wi = (bid - 8192) >> 10;        // 0..2 -> q,k,v
            tile = (bid - 8192) & 1023;
            K = HID_; N = HID_;
            if (wi == 0)      { W = wq; WT = wqkv;               scale = 0.125f; }
            else if (wi == 1) { W = wk; WT = wqkv + 1024 * HID_; }
            else              { W = wv; WT = wqkv + 2048 * HID_; }
        }
        const int ntiles_n = N >> 5;
        const int n0 = (tile % ntiles_n) << 5;
        const int k0 = (tile / ntiles_n) << 5;

        __shared__ float tt[32][33];
#pragma unroll
        for (int i = 0; i < 32; i += 8)
            tt[ty + i][tx] = W[(size_t)(k0 + ty + i) * N + n0 + tx] * scale;
        __syncthreads();
#pragma unroll
        for (int i = 0; i < 32; i += 8)
            WT[(size_t)(n0 + ty + i) * K + k0 + tx] = __float2half(tt[tx][ty + i]);
    } else if (bid < 11276) {
        const int i = (bid - 11264) * 256 + t;   // 0..3071
        if (i < HID_)            bqkv[i] = bq[i] * 0.125f;
        else if (i < 2 * HID_)   bqkv[i] = bk[i - HID_];
        else if (i < 3 * HID_)   bqkv[i] = bv[i - 2 * HID_];
    } else {
        const int i = (bid - 11276) * 256 + t;   // float4 index, 4096 blocks
        const float4 v = ((const float4*)x)[i];
        __half2* o = (__half2*)xh + i * 2;
        o[0] = __floats2half2_rn(v.x, v.y);
        o[1] = __floats2half2_rn(v.z, v.w);
    }
}

// ---------------------------------------------------------------------------
// y = LayerNorm(x + attn) * g + b   (fp32 out + fp16 copy)
// ---------------------------------------------------------------------------
__global__ void ln_kernel(const float* __restrict__ x, const float* __restrict__ attn,
                          const float* __restrict__ gg, const float* __restrict__ bb,
                          float* __restrict__ y, __half* __restrict__ yh)
{
    const int row = blockIdx.x;
    const int t   = threadIdx.x;

    const float4 xv = ((const float4*)(x + (size_t)row * HID_))[t];
    const float4 av = ((const float4*)(attn + (size_t)row * HID_))[t];
    const float v0 = xv.x + av.x, v1 = xv.y + av.y, v2 = xv.z + av.z, v3 = xv.w + av.w;

    float s  = v0 + v1 + v2 + v3;
    float ss = v0 * v0 + v1 * v1 + v2 * v2 + v3 * v3;

    __shared__ float shs[8], shss[8], stats[2];
#pragma unroll
    for (int o = 16; o; o >>= 1) {
        s  += __shfl_xor_sync(0xffffffffu, s, o);
        ss += __shfl_xor_sync(0xffffffffu, ss, o);
    }
    if ((t & 31) == 0) { shs[t >> 5] = s; shss[t >> 5] = ss; }
    __syncthreads();
    if (t == 0) {
        float S = 0.0f, SS = 0.0f;
#pragma unroll
        for (int i = 0; i < 8; i++) { S += shs[i]; SS += shss[i]; }
        const float mu  = S * (1.0f / HID_);
        const float var = SS * (1.0f / HID_) - mu * mu;
        stats[0] = mu;
        stats[1] = rsqrtf(var + 1e-5f);
    }
    __syncthreads();
    const float mu = stats[0], rs = stats[1];

    const float4 g4 = ((const float4*)gg)[t];
    const float4 b4 = ((const float4*)bb)[t];
    float4 o;
    o.x = (v0 - mu) * rs * g4.x + b4.x;
    o.y = (v1 - mu) * rs * g4.y + b4.y;
    o.z = (v2 - mu) * rs * g4.z + b4.z;
    o.w = (v3 - mu) * rs * g4.w + b4.w;
    ((float4*)(y + (size_t)row * HID_))[t] = o;

    __half2* oh = (__half2*)(yh + (size_t)row * HID_) + t * 2;
    oh[0] = __floats2half2_rn(o.x, o.y);
    oh[1] = __floats2half2_rn(o.z, o.w);
}

// ---------------------------------------------------------------------------
extern "C" void kernel_launch(void* const* d_in, const int* in_sizes, int n_in,
                              void* d_out, int out_size)
{
    const float* x    = (const float*)d_in[0];
    const int*   mask = (const int*)  d_in[1];
    const float* wq = (const float*)d_in[2];
    const float* bq = (const float*)d_in[3];
    const float* wk = (const float*)d_in[4];
    const float* bk = (const float*)d_in[5];
    const float* wv = (const float*)d_in[6];
    const float* bv = (const float*)d_in[7];
    // d_in[8..13] dead (global-attention branch is sliced away by [:, :s0]).
    const float* ln_g = (const float*)d_in[14];
    const float* ln_b = (const float*)d_in[15];
    const float* w1 = (const float*)d_in[16];
    const float* b1 = (const float*)d_in[17];
    const float* w2 = (const float*)d_in[18];
    const float* b2 = (const float*)d_in[19];
    float* out = (float*)d_out;

    float *attn, *y, *bqkv;
    __half *qkvh, *yh, *xh, *hh, *wqkv, *w1t, *w2t;
    cudaGetSymbolAddress((void**)&qkvh, g_qkvh);
    cudaGetSymbolAddress((void**)&attn, g_attn);
    cudaGetSymbolAddress((void**)&y,    g_y);
    cudaGetSymbolAddress((void**)&yh,   g_yh);
    cudaGetSymbolAddress((void**)&xh,   g_xh);
    cudaGetSymbolAddress((void**)&hh,   g_hh);
    cudaGetSymbolAddress((void**)&wqkv, g_wqkv);
    cudaGetSymbolAddress((void**)&w1t,  g_w1t);
    cudaGetSymbolAddress((void**)&w2t,  g_w2t);
    cudaGetSymbolAddress((void**)&bqkv, g_bqkv);

    cudaFuncSetAttribute(hgemm<0>, cudaFuncAttributeMaxDynamicSharedMemorySize, HG_SMEM);
    cudaFuncSetAttribute(hgemm<1>, cudaFuncAttributeMaxDynamicSharedMemorySize, HG_SMEM);
    cudaFuncSetAttribute(hgemm<2>, cudaFuncAttributeMaxDynamicSharedMemorySize, HG_SMEM);
    cudaFuncSetAttribute(fattn_kernel, cudaFuncAttributeMaxDynamicSharedMemorySize, FA_SMEM);

    // one fused prep launch (transposes + bias concat + x->fp16)
    prep_kernel<<<PREP_BLOCKS, 256>>>(wq, wk, wv, w1, w2, bq, bk, bv, x,
                                      wqkv, w1t, w2t, bqkv, xh);

    // fused QKV projection -> fp16
    hgemm<0><<<dim3(QKVN_ / 128, NROWS_ / 128), 256, HG_SMEM>>>(
        xh, wqkv, bqkv, nullptr, qkvh, NROWS_, QKVN_, HID_);

    fattn_kernel<<<dim3(BATCH_ * NHEAD_, S0_ / 128), 256, FA_SMEM>>>(
        qkvh, bk, bv, mask, attn);

    ln_kernel<<<NROWS_, 256>>>(x, attn, ln_g, ln_b, y, yh);

    hgemm<1><<<dim3(FFN_ / 128, NROWS_ / 128), 256, HG_SMEM>>>(
        yh, w1t, b1, nullptr, hh, NROWS_, FFN_, HID_);
    hgemm<2><<<dim3(HID_ / 128, NROWS_ / 128), 256, HG_SMEM>>>(
        hh, w2t, b2, y, out, NROWS_, HID_, FFN_);
}